// round 3
// baseline (speedup 1.0000x reference)
#include <cuda_runtime.h>

#define NN 50000
#define EE 800000

// ---- scratch (static device arrays; no allocation) ----
__device__ __align__(256) float d_g[NN * 64];   // folded node projection g[n][h*8+k]
__device__ __align__(256) float d_Wg[64 * 128]; // W_att folded into W
__device__ __align__(256) float d_Wc8[128];     // 8 * (W_edge_att @ W_edge)  [8][16]
__device__ __align__(256) float d_S[NN * 8];    // per-node, per-head sum of exp
__device__ __align__(256) float d_Z[8];         // global per-head softmax denominator
__device__ int d_is64;                          // 1 if edge_index is int64, 0 if int32

// ---------------------------------------------------------------------------
__global__ void zero_kernel() {
    int i = blockIdx.x * blockDim.x + threadIdx.x;
    if (i < NN * 8) d_S[i] = 0.f;
    if (i < 8) d_Z[i] = 0.f;
}

// ---------------------------------------------------------------------------
// Detect edge_index dtype. For int64 (little-endian, values < 2^31) every odd
// 32-bit word is zero; for int32 data those words are random node indices.
__global__ void detect_idx_kernel(const int* __restrict__ ei_words) {
    int t = threadIdx.x;
    int w = ei_words[2 * t + 1];                 // high half if int64
    unsigned any = __ballot_sync(0xffffffffu, w != 0);
    __shared__ int nz;
    if (t == 0) nz = 0;
    __syncthreads();
    if ((t & 31) == 0 && any) atomicOr(&nz, 1);
    __syncthreads();
    if (t == 0) d_is64 = nz ? 0 : 1;
}

// ---------------------------------------------------------------------------
// Fold small weight matrices (runs every launch; tiny).
__global__ void prep_kernel(const float* __restrict__ W,
                            const float* __restrict__ W_edge,
                            const float* __restrict__ W_edge_att,
                            const float* __restrict__ W_att) {
    int i = blockIdx.x * blockDim.x + threadIdx.x;
    if (i < 64 * 128) {
        int j = i >> 7, c = i & 127;
        int hh = j >> 3, k = j & 7;
        float acc = 0.f;
#pragma unroll
        for (int d = 0; d < 8; d++)
            acc += W_att[k * 8 + d] * W[(hh * 8 + d) * 128 + c];
        d_Wg[i] = acc;
    } else if (i < 64 * 128 + 128) {
        int ii = i - 64 * 128;
        int h = ii >> 4, q = ii & 15;
        float acc = 0.f;
        for (int m = 0; m < 64; m++)
            acc += W_edge_att[h * 64 + m] * W_edge[m * 16 + q];
        d_Wc8[ii] = 8.0f * acc;   // edge_term = ea * D, D folded here
    }
}

// ---------------------------------------------------------------------------
// g = x @ Wg.T : [N,128] x [128,64] -> [N,64]; 64x64 tile per block,
// 4x4 register micro-tile.
__global__ void __launch_bounds__(256) gemm_g_kernel(const float* __restrict__ x,
                                                     int n) {
    __shared__ float xs[64][68];
    __shared__ float ws[64][68];
    int t = threadIdx.x;
    int tx = t & 15, ty = t >> 4;
    int n0 = blockIdx.x * 64;
    float acc[4][4];
#pragma unroll
    for (int r = 0; r < 4; r++)
#pragma unroll
        for (int s = 0; s < 4; s++) acc[r][s] = 0.f;

    for (int kc = 0; kc < 128; kc += 64) {
#pragma unroll
        for (int i = 0; i < 4; i++) {
            int idx = t + i * 256;       // 1024 float4 slots = 64 rows x 16
            int m = idx >> 4;
            int kq = idx & 15;
            float4 v = make_float4(0.f, 0.f, 0.f, 0.f);
            if (n0 + m < n)
                v = *reinterpret_cast<const float4*>(
                        x + (size_t)(n0 + m) * 128 + kc + kq * 4);
            *reinterpret_cast<float4*>(&xs[m][kq * 4]) = v;
            float4 w = *reinterpret_cast<const float4*>(
                    d_Wg + m * 128 + kc + kq * 4);
            *reinterpret_cast<float4*>(&ws[m][kq * 4]) = w;
        }
        __syncthreads();
#pragma unroll
        for (int k4 = 0; k4 < 16; k4++) {
            float4 a[4], b[4];
#pragma unroll
            for (int r = 0; r < 4; r++)
                a[r] = *reinterpret_cast<const float4*>(&xs[ty * 4 + r][k4 * 4]);
#pragma unroll
            for (int s = 0; s < 4; s++)
                b[s] = *reinterpret_cast<const float4*>(&ws[tx + 16 * s][k4 * 4]);
#pragma unroll
            for (int r = 0; r < 4; r++)
#pragma unroll
                for (int s = 0; s < 4; s++)
                    acc[r][s] += a[r].x * b[s].x + a[r].y * b[s].y +
                                 a[r].z * b[s].z + a[r].w * b[s].w;
        }
        __syncthreads();
    }
#pragma unroll
    for (int r = 0; r < 4; r++) {
        int m = n0 + ty * 4 + r;
        if (m < n) {
#pragma unroll
            for (int s = 0; s < 4; s++)
                d_g[(size_t)m * 64 + tx + 16 * s] = acc[r][s];
        }
    }
}

// ---------------------------------------------------------------------------
// One pass over all edges: folded edge MLP, gather g[src]/g[dst], dot per
// head, leaky_relu, exp (no max-shift needed: bounded inputs), scatter-add
// exp into S[dst], block-reduce exp sums into Z.
__global__ void __launch_bounds__(256) edge_kernel(const float* __restrict__ edge_attr,
                                                   const void* __restrict__ eidx,
                                                   int E) {
    __shared__ float swc[128];
    __shared__ float sred[8][8];
    int t = threadIdx.x;
    if (t < 128) swc[t] = d_Wc8[t];
    __syncthreads();

    int e = blockIdx.x * blockDim.x + t;
    float p[8];
    if (e < E) {
        int s, d;
        if (d_is64) {
            const long long* ei = (const long long*)eidx;
            s = (int)ei[e];
            d = (int)ei[E + e];
        } else {
            const int* ei = (const int*)eidx;
            s = ei[e];
            d = ei[E + e];
        }
        const float4* q4 =
            reinterpret_cast<const float4*>(edge_attr + (size_t)e * 16);
        float4 q0 = q4[0], q1 = q4[1], q2 = q4[2], q3 = q4[3];
        const float4* gs =
            reinterpret_cast<const float4*>(d_g + (size_t)s * 64);
        const float4* gd =
            reinterpret_cast<const float4*>(d_g + (size_t)d * 64);
#pragma unroll
        for (int h = 0; h < 8; h++) {
            const float* wc = swc + h * 16;
            float a = wc[0] * q0.x + wc[1] * q0.y + wc[2] * q0.z + wc[3] * q0.w
                    + wc[4] * q1.x + wc[5] * q1.y + wc[6] * q1.z + wc[7] * q1.w
                    + wc[8] * q2.x + wc[9] * q2.y + wc[10] * q2.z + wc[11] * q2.w
                    + wc[12] * q3.x + wc[13] * q3.y + wc[14] * q3.z + wc[15] * q3.w;
            float4 a0 = gs[2 * h], a1 = gs[2 * h + 1];
            float4 b0 = gd[2 * h], b1 = gd[2 * h + 1];
            a += a0.x * b0.x + a0.y * b0.y + a0.z * b0.z + a0.w * b0.w
               + a1.x * b1.x + a1.y * b1.y + a1.z * b1.z + a1.w * b1.w;
            a = a > 0.f ? a : 0.2f * a;        // leaky_relu(0.2)
            p[h] = __expf(a);
        }
        float* Sp = d_S + (size_t)d * 8;
#pragma unroll
        for (int h = 0; h < 8; h++) atomicAdd(Sp + h, p[h]);
    } else {
#pragma unroll
        for (int h = 0; h < 8; h++) p[h] = 0.f;
    }

    // block-level reduction of exp-sums into Z[8]
#pragma unroll
    for (int h = 0; h < 8; h++) {
#pragma unroll
        for (int off = 16; off > 0; off >>= 1)
            p[h] += __shfl_down_sync(0xffffffffu, p[h], off);
    }
    int lane = t & 31, wid = t >> 5;
    if (lane == 0) {
#pragma unroll
        for (int h = 0; h < 8; h++) sred[wid][h] = p[h];
    }
    __syncthreads();
    if (t < 8) {
        float z = 0.f;
#pragma unroll
        for (int w = 0; w < 8; w++) z += sred[w][t];
        atomicAdd(&d_Z[t], z);
    }
}

// ---------------------------------------------------------------------------
// out[v] = relu( W_out @ (g[v] * S[v,h]/Z[h]) )
__global__ void __launch_bounds__(256) out_kernel(const float* __restrict__ Wout,
                                                  float* __restrict__ out, int n) {
    int v = blockIdx.x * blockDim.x + threadIdx.x;
    if (v >= n) return;
    float t8[8];
    const float* Sp = d_S + (size_t)v * 8;
#pragma unroll
    for (int h = 0; h < 8; h++) t8[h] = Sp[h] / d_Z[h];
    float acc[8];
#pragma unroll
    for (int i = 0; i < 8; i++) acc[i] = 0.f;
    const float4* g4 = reinterpret_cast<const float4*>(d_g + (size_t)v * 64);
#pragma unroll
    for (int jq = 0; jq < 16; jq++) {
        float4 gv = g4[jq];
        float tt = t8[jq >> 1];
        gv.x *= tt; gv.y *= tt; gv.z *= tt; gv.w *= tt;
#pragma unroll
        for (int i = 0; i < 8; i++) {
            float4 w = *reinterpret_cast<const float4*>(Wout + i * 64 + jq * 4);
            acc[i] += gv.x * w.x + gv.y * w.y + gv.z * w.z + gv.w * w.w;
        }
    }
#pragma unroll
    for (int i = 0; i < 8; i++)
        out[(size_t)v * 8 + i] = fmaxf(acc[i], 0.f);
}

// ---------------------------------------------------------------------------
extern "C" void kernel_launch(void* const* d_in, const int* in_sizes, int n_in,
                              void* d_out, int out_size) {
    const float* x          = (const float*)d_in[0];
    const float* edge_attr  = (const float*)d_in[1];
    const float* W          = (const float*)d_in[2];
    const float* W_edge     = (const float*)d_in[3];
    const float* W_edge_att = (const float*)d_in[4];
    const float* W_att      = (const float*)d_in[5];
    const float* W_out      = (const float*)d_in[6];
    const void*  eidx       = (const void*)d_in[7];
    int N = in_sizes[0] / 128;   // 50000
    int E = in_sizes[7] / 2;     // 800000

    detect_idx_kernel<<<1, 256>>>((const int*)eidx);
    zero_kernel<<<(NN * 8 + 255) / 256, 256>>>();
    prep_kernel<<<33, 256>>>(W, W_edge, W_edge_att, W_att);
    gemm_g_kernel<<<(N + 63) / 64, 256>>>(x, N);
    edge_kernel<<<(E + 255) / 256, 256>>>(edge_attr, eidx, E);
    out_kernel<<<(N + 255) / 256, 256>>>(W_out, (float*)d_out, N);
}

// round 4
// speedup vs baseline: 1.3048x; 1.3048x over previous
#include <cuda_runtime.h>

#define NN 50000
#define EE 800000

// ---- scratch (static device arrays; no allocation) ----
__device__ __align__(256) float d_g[NN * 64];   // folded node projection g[n][h*8+k]
__device__ __align__(256) float d_Wg[64 * 128]; // W_att folded into W
__device__ __align__(256) float d_Wc8[128];     // 8 * (W_edge_att @ W_edge)  [8][16]
__device__ __align__(256) float d_S[NN * 8];    // per-node, per-head sum of exp
__device__ __align__(256) float d_Z[8];         // global per-head softmax denominator
__device__ int d_is64;                          // 1 if edge_index is int64, 0 if int32

#define ZERO_BLOCKS 1563   // ceil(NN*8/256)
#define PREP_BLOCKS 33

// ---------------------------------------------------------------------------
// Fused: zero S/Z + fold small weights + detect edge_index dtype.
__global__ void prep_all_kernel(const float* __restrict__ W,
                                const float* __restrict__ W_edge,
                                const float* __restrict__ W_edge_att,
                                const float* __restrict__ W_att,
                                const int* __restrict__ ei_words) {
    int b = blockIdx.x;
    int t = threadIdx.x;
    if (b < ZERO_BLOCKS) {
        int i = b * 256 + t;
        if (i < NN * 8) d_S[i] = 0.f;
        if (b == 0 && t < 8) d_Z[t] = 0.f;
    } else if (b < ZERO_BLOCKS + PREP_BLOCKS) {
        int i = (b - ZERO_BLOCKS) * 256 + t;
        if (i < 64 * 128) {
            int j = i >> 7, c = i & 127;
            int hh = j >> 3, k = j & 7;
            float acc = 0.f;
#pragma unroll
            for (int d = 0; d < 8; d++)
                acc += W_att[k * 8 + d] * W[(hh * 8 + d) * 128 + c];
            d_Wg[i] = acc;
        } else if (i < 64 * 128 + 128) {
            int ii = i - 64 * 128;
            int h = ii >> 4, q = ii & 15;
            float acc = 0.f;
            for (int m = 0; m < 64; m++)
                acc += W_edge_att[h * 64 + m] * W_edge[m * 16 + q];
            d_Wc8[ii] = 8.0f * acc;   // edge_term = ea * D, D folded here
        }
    } else {
        // dtype detect: int64 little-endian values < 2^31 -> odd words all 0
        int w = ei_words[2 * t + 1];
        unsigned any = __ballot_sync(0xffffffffu, w != 0);
        __shared__ int nz;
        if (t == 0) nz = 0;
        __syncthreads();
        if ((t & 31) == 0 && any) atomicOr(&nz, 1);
        __syncthreads();
        if (t == 0) d_is64 = nz ? 0 : 1;
    }
}

// ---------------------------------------------------------------------------
// g = x @ Wg.T : [N,128] x [128,64] -> [N,64]
// 128x64 tile per block (256 threads), 8x4 register micro-tile, K-chunks of 32.
__global__ void __launch_bounds__(256) gemm_g_kernel(const float* __restrict__ x,
                                                     int n) {
    __shared__ float xs[128][36];
    __shared__ float ws[64][36];
    int t = threadIdx.x;
    int tx = t & 15, ty = t >> 4;
    int n0 = blockIdx.x * 128;
    float acc[8][4];
#pragma unroll
    for (int r = 0; r < 8; r++)
#pragma unroll
        for (int s = 0; s < 4; s++) acc[r][s] = 0.f;

    for (int kc = 0; kc < 128; kc += 32) {
#pragma unroll
        for (int i = 0; i < 4; i++) {        // 1024 float4 = 128 rows x 8
            int idx = t + i * 256;
            int m = idx >> 3;
            int kq = idx & 7;
            float4 v = make_float4(0.f, 0.f, 0.f, 0.f);
            if (n0 + m < n)
                v = *reinterpret_cast<const float4*>(
                        x + (size_t)(n0 + m) * 128 + kc + kq * 4);
            *reinterpret_cast<float4*>(&xs[m][kq * 4]) = v;
        }
#pragma unroll
        for (int i = 0; i < 2; i++) {        // 512 float4 = 64 rows x 8
            int idx = t + i * 256;
            int m = idx >> 3;
            int kq = idx & 7;
            float4 w = *reinterpret_cast<const float4*>(
                    d_Wg + m * 128 + kc + kq * 4);
            *reinterpret_cast<float4*>(&ws[m][kq * 4]) = w;
        }
        __syncthreads();
#pragma unroll
        for (int k4 = 0; k4 < 8; k4++) {
            float4 b[4];
#pragma unroll
            for (int s = 0; s < 4; s++)
                b[s] = *reinterpret_cast<const float4*>(&ws[tx + 16 * s][k4 * 4]);
#pragma unroll
            for (int r = 0; r < 8; r++) {
                float4 a = *reinterpret_cast<const float4*>(&xs[ty * 8 + r][k4 * 4]);
#pragma unroll
                for (int s = 0; s < 4; s++)
                    acc[r][s] += a.x * b[s].x + a.y * b[s].y +
                                 a.z * b[s].z + a.w * b[s].w;
            }
        }
        __syncthreads();
    }
#pragma unroll
    for (int r = 0; r < 8; r++) {
        int m = n0 + ty * 8 + r;
        if (m < n) {
#pragma unroll
            for (int s = 0; s < 4; s++)
                d_g[(size_t)m * 64 + tx + 16 * s] = acc[r][s];
        }
    }
}

// ---------------------------------------------------------------------------
// Edge pass, head-per-thread: 8 threads per edge (one per head), 32 edges per
// 256-thread block tile, grid-stride over tiles. Group's g loads are
// contiguous 256 B per row -> coalesced; 1 RED per thread into a shared 32 B
// sector; Z accumulated in registers, one atomic per block at the end.
__global__ void __launch_bounds__(256) edge_kernel(const float* __restrict__ edge_attr,
                                                   const void* __restrict__ eidx,
                                                   int E) {
    __shared__ float sA[32 * 17];
    __shared__ float sred[8][8];
    int t = threadIdx.x;
    int grp = t >> 3, h = t & 7;
    int is64 = d_is64;

    float wc[16];
#pragma unroll
    for (int q = 0; q < 16; q++) wc[q] = d_Wc8[h * 16 + q];

    float zacc = 0.f;
    int ntiles = (E + 31) >> 5;
    for (int tile = blockIdx.x; tile < ntiles; tile += gridDim.x) {
        int base = tile << 5;
        __syncthreads();                      // protect smem reuse
        {
            int idx = 2 * t;                  // float offset within tile
            int e = idx >> 4, q = idx & 15;
            float2 v = make_float2(0.f, 0.f);
            if (base + e < E)
                v = *reinterpret_cast<const float2*>(
                        edge_attr + (size_t)(base + e) * 16 + q);
            sA[e * 17 + q] = v.x;
            sA[e * 17 + q + 1] = v.y;
        }
        __syncthreads();

        int e = base + grp;
        float p = 0.f;
        if (e < E) {
            int s, d;
            if (is64) {
                const long long* ei = (const long long*)eidx;
                s = (int)ei[e];
                d = (int)ei[E + e];
            } else {
                const int* ei = (const int*)eidx;
                s = ei[e];
                d = ei[E + e];
            }
            const float4* gs =
                reinterpret_cast<const float4*>(d_g + (size_t)s * 64 + h * 8);
            const float4* gd =
                reinterpret_cast<const float4*>(d_g + (size_t)d * 64 + h * 8);
            float4 a0 = gs[0], a1 = gs[1];
            float4 b0 = gd[0], b1 = gd[1];
            const float* ap = sA + grp * 17;
            float a = 0.f;
#pragma unroll
            for (int q = 0; q < 16; q++) a = fmaf(wc[q], ap[q], a);
            a += a0.x * b0.x + a0.y * b0.y + a0.z * b0.z + a0.w * b0.w
               + a1.x * b1.x + a1.y * b1.y + a1.z * b1.z + a1.w * b1.w;
            a = a > 0.f ? a : 0.2f * a;       // leaky_relu(0.2)
            p = __expf(a);
            atomicAdd(d_S + (size_t)d * 8 + h, p);
        }
        zacc += p;
    }

    // Z reduction: sum over lanes with the same head within the warp
    zacc += __shfl_xor_sync(0xffffffffu, zacc, 8);
    zacc += __shfl_xor_sync(0xffffffffu, zacc, 16);
    int lane = t & 31, wid = t >> 5;
    __syncthreads();
    if (lane < 8) sred[wid][lane] = zacc;
    __syncthreads();
    if (t < 8) {
        float z = 0.f;
#pragma unroll
        for (int w = 0; w < 8; w++) z += sred[w][t];
        atomicAdd(&d_Z[t], z);
    }
}

// ---------------------------------------------------------------------------
// out[v] = relu( W_out @ (g[v] * S[v,h]/Z[h]) )
__global__ void __launch_bounds__(256) out_kernel(const float* __restrict__ Wout,
                                                  float* __restrict__ out, int n) {
    int v = blockIdx.x * blockDim.x + threadIdx.x;
    if (v >= n) return;
    float t8[8];
    const float* Sp = d_S + (size_t)v * 8;
#pragma unroll
    for (int h = 0; h < 8; h++) t8[h] = Sp[h] / d_Z[h];
    float acc[8];
#pragma unroll
    for (int i = 0; i < 8; i++) acc[i] = 0.f;
    const float4* g4 = reinterpret_cast<const float4*>(d_g + (size_t)v * 64);
#pragma unroll
    for (int jq = 0; jq < 16; jq++) {
        float4 gv = g4[jq];
        float tt = t8[jq >> 1];
        gv.x *= tt; gv.y *= tt; gv.z *= tt; gv.w *= tt;
#pragma unroll
        for (int i = 0; i < 8; i++) {
            float4 w = *reinterpret_cast<const float4*>(Wout + i * 64 + jq * 4);
            acc[i] += gv.x * w.x + gv.y * w.y + gv.z * w.z + gv.w * w.w;
        }
    }
#pragma unroll
    for (int i = 0; i < 8; i++)
        out[(size_t)v * 8 + i] = fmaxf(acc[i], 0.f);
}

// ---------------------------------------------------------------------------
extern "C" void kernel_launch(void* const* d_in, const int* in_sizes, int n_in,
                              void* d_out, int out_size) {
    const float* x          = (const float*)d_in[0];
    const float* edge_attr  = (const float*)d_in[1];
    const float* W          = (const float*)d_in[2];
    const float* W_edge     = (const float*)d_in[3];
    const float* W_edge_att = (const float*)d_in[4];
    const float* W_att      = (const float*)d_in[5];
    const float* W_out      = (const float*)d_in[6];
    const void*  eidx       = (const void*)d_in[7];
    int N = in_sizes[0] / 128;   // 50000
    int E = in_sizes[7] / 2;     // 800000

    prep_all_kernel<<<ZERO_BLOCKS + PREP_BLOCKS + 1, 256>>>(
        W, W_edge, W_edge_att, W_att, (const int*)eidx);
    gemm_g_kernel<<<(N + 127) / 128, 256>>>(x, N);
    edge_kernel<<<1184, 256>>>(edge_attr, eidx, E);
    out_kernel<<<(N + 255) / 256, 256>>>(W_out, (float*)d_out, N);
}